// round 11
// baseline (speedup 1.0000x reference)
#include <cuda_runtime.h>
#include <cuda_bf16.h>

#define NUM_CLASSES 20
#define B_SIZE      128
#define N_GT        50
#define TOTAL_GT    (B_SIZE * N_GT)        // 6400
#define QUADS_PER_GT 5                     // 20 classes = 5 x float4
#define TOTAL_WORK  (TOTAL_GT * QUADS_PER_GT)  // 32000
#define THREADS     640                    // 20 warps
#define BLOCKS      (TOTAL_WORK / THREADS)     // 50 (exact, one wave)
#define NWARPS      (THREADS / 32)             // 20

// Accumulators padded to separate 256B-aligned lines so the two float
// reductions and the counter hash to different LTS partitions and their
// atomics do not serialize on one L2 atomic ALU. Self-resetting: the last
// block zeroes them after finalizing, so every graph replay is identical.
struct __align__(256) PaddedF { float v;        unsigned char pad[252]; };
struct __align__(256) PaddedU { unsigned int v; unsigned char pad[252]; };
__device__ PaddedF g_box = {0.0f, {0}};
__device__ PaddedF g_cls = {0.0f, {0}};
__device__ PaddedU g_done = {0u, {0}};

__global__ void __launch_bounds__(THREADS)
yolo_loss_kernel(const float* __restrict__ cls0, const float* __restrict__ box0,
                 const float* __restrict__ cls1, const float* __restrict__ box1,
                 const float* __restrict__ cls2, const float* __restrict__ box2,
                 const float* __restrict__ gt_boxes,
                 const int*   __restrict__ gt_labels,
                 float* __restrict__ out)
{
    const int t  = blockIdx.x * THREADS + threadIdx.x;  // 0..31999
    const int gt = t / QUADS_PER_GT;                    // 0..6399
    const int q  = t - gt * QUADS_PER_GT;               // 0..4
    const int b  = gt / N_GT;                           // batch index

    // GT box in pixel coords (5 threads share it: warp-broadcast L1 hit)
    const float4 gb = __ldg(reinterpret_cast<const float4*>(gt_boxes) + gt);
    const int label = __ldg(gt_labels + gt);            // issued concurrently

    const float x1 = gb.x * 640.0f;
    const float y1 = gb.y * 640.0f;
    const float x2 = gb.z * 640.0f;
    const float y2 = gb.w * 640.0f;

    const float bw   = x2 - x1;
    const float bh   = y2 - y1;
    const float area = bw * bh;

    // scale selection: 0 small (<160^2), 1 medium (<320^2), 2 large
    const int s = (area < 25600.0f) ? 0 : ((area < 102400.0f) ? 1 : 2);

    const int   G          = 80 >> s;                        // 80, 40, 20
    const float stride     = (float)(8 << s);                // 8, 16, 32 (exact)
    const float inv_stride = (s == 0) ? 0.125f
                           : (s == 1) ? 0.0625f : 0.03125f;  // exact pow2

    const float cx = (x1 + x2) * 0.5f;
    const float cy = (y1 + y2) * 0.5f;

    // truncation toward zero matches jnp astype(int32); cx,cy >= 0 here
    int gx = (int)(cx * inv_stride);
    int gy = (int)(cy * inv_stride);
    gx = min(max(gx, 0), G - 1);
    gy = min(max(gy, 0), G - 1);

    const int cell = (b * G + gy) * G + gx;

    // ---- BCE: 4 classes per thread via one LDG.128 ----
    // cls row is 80 bytes at offset cell*80 -> 16B aligned, so float4 is legal.
    const float* clsP = (s == 0) ? cls0 : ((s == 1) ? cls1 : cls2);
    const float4 pv = __ldg(reinterpret_cast<const float4*>(clsP + cell * NUM_CLASSES) + q);

    // fast log: p is uniform(0,1); rel-err budget 1e-3 >> __logf error.
    const int c0 = q * 4;
    float v0 = __logf((c0 + 0 == label) ? pv.x : (1.0f - pv.x));
    float v1 = __logf((c0 + 1 == label) ? pv.y : (1.0f - pv.y));
    float v2 = __logf((c0 + 2 == label) ? pv.z : (1.0f - pv.z));
    float v3 = __logf((c0 + 3 == label) ? pv.w : (1.0f - pv.w));
    v0 = fmaxf(v0, -100.0f);
    v1 = fmaxf(v1, -100.0f);
    v2 = fmaxf(v2, -100.0f);
    v3 = fmaxf(v3, -100.0f);
    float cls_l = -((v0 + v1) + (v2 + v3)) * (1.0f / (float)NUM_CLASSES);

    // ---- box decode + IoU: one lane per GT ----
    float box_l = 0.0f;
    if (q == 0) {
        const float* boxP = (s == 0) ? box0 : ((s == 1) ? box1 : box2);
        const float4 pb = __ldg(reinterpret_cast<const float4*>(boxP) + cell);
        const float px = ((float)gx + pb.x) * stride;
        const float py = ((float)gy + pb.y) * stride;
        const float pw = pb.z * 640.0f;
        const float ph = pb.w * 640.0f;

        const float px1 = px - pw * 0.5f;
        const float py1 = py - ph * 0.5f;
        const float px2 = px + pw * 0.5f;
        const float py2 = py + ph * 0.5f;

        const float ix1 = fmaxf(px1, x1);
        const float iy1 = fmaxf(py1, y1);
        const float ix2 = fminf(px2, x2);
        const float iy2 = fminf(py2, y2);

        const float inter = fmaxf(ix2 - ix1, 0.0f) * fmaxf(iy2 - iy1, 0.0f);
        const float a1    = (px2 - px1) * (py2 - py1);
        const float iou   = __fdividef(inter, a1 + area - inter + 1e-6f);

        box_l = 1.0f - iou;
    }

    // ---- reduction: warp shuffle -> 1 barrier -> warp 0 ----
    #pragma unroll
    for (int off = 16; off > 0; off >>= 1) {
        box_l += __shfl_down_sync(0xFFFFFFFFu, box_l, off);
        cls_l += __shfl_down_sync(0xFFFFFFFFu, cls_l, off);
    }

    __shared__ float sb[NWARPS];
    __shared__ float sc[NWARPS];
    const int wid = threadIdx.x >> 5;
    const int lid = threadIdx.x & 31;
    if (lid == 0) { sb[wid] = box_l; sc[wid] = cls_l; }
    __syncthreads();

    if (wid == 0) {
        float vb = (lid < NWARPS) ? sb[lid] : 0.0f;
        float vc = (lid < NWARPS) ? sc[lid] : 0.0f;
        #pragma unroll
        for (int off = 16; off > 0; off >>= 1) {
            vb += __shfl_down_sync(0xFFFFFFFFu, vb, off);
            vc += __shfl_down_sync(0xFFFFFFFFu, vc, off);
        }
        if (lid == 0) {
            atomicAdd(&g_box.v, vb);   // REDG (no return use)
            atomicAdd(&g_cls.v, vc);   // different 256B line -> parallel LTS
            __threadfence();
            // atomicInc wraps old==BLOCKS-1 -> 0, so g_done self-resets
            const unsigned int prev = atomicInc(&g_done.v, BLOCKS - 1);
            if (prev == BLOCKS - 1) {
                const float box_loss = g_box.v * (1.0f / (float)TOTAL_GT);
                const float cls_loss = g_cls.v * (1.0f / (float)TOTAL_GT);
                out[0] = 7.5f * box_loss + 0.5f * cls_loss;
                out[1] = box_loss;
                out[2] = cls_loss;
                out[3] = 0.0f;
                g_box.v = 0.0f;
                g_cls.v = 0.0f;
            }
        }
    }
}

extern "C" void kernel_launch(void* const* d_in, const int* in_sizes, int n_in,
                              void* d_out, int out_size)
{
    const float* cls0     = (const float*)d_in[0];
    const float* box0     = (const float*)d_in[1];
    const float* cls1     = (const float*)d_in[2];
    const float* box1     = (const float*)d_in[3];
    const float* cls2     = (const float*)d_in[4];
    const float* box2     = (const float*)d_in[5];
    const float* gt_boxes = (const float*)d_in[6];
    const int*   gt_labels= (const int*)d_in[7];
    float*       out      = (float*)d_out;

    yolo_loss_kernel<<<BLOCKS, THREADS>>>(cls0, box0, cls1, box1, cls2, box2,
                                          gt_boxes, gt_labels, out);
}

// round 12
// speedup vs baseline: 1.0145x; 1.0145x over previous
#include <cuda_runtime.h>
#include <cuda_bf16.h>

#define NUM_CLASSES 20
#define B_SIZE      128
#define N_GT        50
#define TOTAL_GT    (B_SIZE * N_GT)        // 6400
#define QUADS_PER_GT 5                     // 20 classes = 5 x float4
#define TOTAL_WORK  (TOTAL_GT * QUADS_PER_GT)  // 32000
#define THREADS     320                    // 10 warps
#define BLOCKS      (TOTAL_WORK / THREADS)     // 100 (exact, one wave)
#define NWARPS      (THREADS / 32)             // 10

// Accumulators padded to separate 256B-aligned lines so the two float
// reductions and the counter hash to different LTS partitions and their
// atomics do not serialize on one L2 atomic ALU. Self-resetting: the last
// block zeroes them after finalizing, so every graph replay is identical.
struct __align__(256) PaddedF { float v;        unsigned char pad[252]; };
struct __align__(256) PaddedU { unsigned int v; unsigned char pad[252]; };
__device__ PaddedF g_box = {0.0f, {0}};
__device__ PaddedF g_cls = {0.0f, {0}};
__device__ PaddedU g_done = {0u, {0}};

__global__ void __launch_bounds__(THREADS)
yolo_loss_kernel(const float* __restrict__ cls0, const float* __restrict__ box0,
                 const float* __restrict__ cls1, const float* __restrict__ box1,
                 const float* __restrict__ cls2, const float* __restrict__ box2,
                 const float* __restrict__ gt_boxes,
                 const int*   __restrict__ gt_labels,
                 float* __restrict__ out)
{
    const int t  = blockIdx.x * THREADS + threadIdx.x;  // 0..31999
    const int gt = t / QUADS_PER_GT;                    // 0..6399
    const int q  = t - gt * QUADS_PER_GT;               // 0..4
    const int b  = gt / N_GT;                           // batch index

    // GT box in pixel coords (5 threads share it: warp-broadcast L1 hit)
    const float4 gb = __ldg(reinterpret_cast<const float4*>(gt_boxes) + gt);
    const int label = __ldg(gt_labels + gt);            // issued concurrently

    const float x1 = gb.x * 640.0f;
    const float y1 = gb.y * 640.0f;
    const float x2 = gb.z * 640.0f;
    const float y2 = gb.w * 640.0f;

    const float bw   = x2 - x1;
    const float bh   = y2 - y1;
    const float area = bw * bh;

    // scale selection: 0 small (<160^2), 1 medium (<320^2), 2 large
    const int s = (area < 25600.0f) ? 0 : ((area < 102400.0f) ? 1 : 2);

    const int   G          = 80 >> s;                        // 80, 40, 20
    const float stride     = (float)(8 << s);                // 8, 16, 32 (exact)
    const float inv_stride = (s == 0) ? 0.125f
                           : (s == 1) ? 0.0625f : 0.03125f;  // exact pow2

    const float cx = (x1 + x2) * 0.5f;
    const float cy = (y1 + y2) * 0.5f;

    // truncation toward zero matches jnp astype(int32); cx,cy >= 0 here
    int gx = (int)(cx * inv_stride);
    int gy = (int)(cy * inv_stride);
    gx = min(max(gx, 0), G - 1);
    gy = min(max(gy, 0), G - 1);

    const int cell = (b * G + gy) * G + gx;

    // ---- BCE: 4 classes per thread via one LDG.128 ----
    // cls row is 80 bytes at offset cell*80 -> 16B aligned, so float4 is legal.
    const float* clsP = (s == 0) ? cls0 : ((s == 1) ? cls1 : cls2);
    const float4 pv = __ldg(reinterpret_cast<const float4*>(clsP + cell * NUM_CLASSES) + q);

    // fast log: p is uniform(0,1); rel-err budget 1e-3 >> __logf error.
    const int c0 = q * 4;
    float v0 = __logf((c0 + 0 == label) ? pv.x : (1.0f - pv.x));
    float v1 = __logf((c0 + 1 == label) ? pv.y : (1.0f - pv.y));
    float v2 = __logf((c0 + 2 == label) ? pv.z : (1.0f - pv.z));
    float v3 = __logf((c0 + 3 == label) ? pv.w : (1.0f - pv.w));
    v0 = fmaxf(v0, -100.0f);
    v1 = fmaxf(v1, -100.0f);
    v2 = fmaxf(v2, -100.0f);
    v3 = fmaxf(v3, -100.0f);
    float cls_l = -((v0 + v1) + (v2 + v3)) * (1.0f / (float)NUM_CLASSES);

    // ---- box decode + IoU: one lane per GT ----
    float box_l = 0.0f;
    if (q == 0) {
        const float* boxP = (s == 0) ? box0 : ((s == 1) ? box1 : box2);
        const float4 pb = __ldg(reinterpret_cast<const float4*>(boxP) + cell);
        const float px = ((float)gx + pb.x) * stride;
        const float py = ((float)gy + pb.y) * stride;
        const float pw = pb.z * 640.0f;
        const float ph = pb.w * 640.0f;

        const float px1 = px - pw * 0.5f;
        const float py1 = py - ph * 0.5f;
        const float px2 = px + pw * 0.5f;
        const float py2 = py + ph * 0.5f;

        const float ix1 = fmaxf(px1, x1);
        const float iy1 = fmaxf(py1, y1);
        const float ix2 = fminf(px2, x2);
        const float iy2 = fminf(py2, y2);

        const float inter = fmaxf(ix2 - ix1, 0.0f) * fmaxf(iy2 - iy1, 0.0f);
        const float a1    = (px2 - px1) * (py2 - py1);
        const float iou   = __fdividef(inter, a1 + area - inter + 1e-6f);

        box_l = 1.0f - iou;
    }

    // ---- reduction: warp shuffle -> 1 barrier -> warp 0 ----
    #pragma unroll
    for (int off = 16; off > 0; off >>= 1) {
        box_l += __shfl_down_sync(0xFFFFFFFFu, box_l, off);
        cls_l += __shfl_down_sync(0xFFFFFFFFu, cls_l, off);
    }

    __shared__ float sb[NWARPS];
    __shared__ float sc[NWARPS];
    const int wid = threadIdx.x >> 5;
    const int lid = threadIdx.x & 31;
    if (lid == 0) { sb[wid] = box_l; sc[wid] = cls_l; }
    __syncthreads();

    if (wid == 0) {
        float vb = (lid < NWARPS) ? sb[lid] : 0.0f;
        float vc = (lid < NWARPS) ? sc[lid] : 0.0f;
        #pragma unroll
        for (int off = 8; off > 0; off >>= 1) {   // NWARPS=10 <= 16 lanes
            vb += __shfl_down_sync(0xFFFFFFFFu, vb, off);
            vc += __shfl_down_sync(0xFFFFFFFFu, vc, off);
        }
        if (lid == 0) {
            atomicAdd(&g_box.v, vb);   // padded: separate LTS lines,
            atomicAdd(&g_cls.v, vc);   // adds proceed in parallel
            __threadfence();
            // atomicInc wraps old==BLOCKS-1 -> 0, so g_done self-resets
            const unsigned int prev = atomicInc(&g_done.v, BLOCKS - 1);
            if (prev == BLOCKS - 1) {
                const float box_loss = g_box.v * (1.0f / (float)TOTAL_GT);
                const float cls_loss = g_cls.v * (1.0f / (float)TOTAL_GT);
                out[0] = 7.5f * box_loss + 0.5f * cls_loss;
                out[1] = box_loss;
                out[2] = cls_loss;
                out[3] = 0.0f;
                g_box.v = 0.0f;
                g_cls.v = 0.0f;
            }
        }
    }
}

extern "C" void kernel_launch(void* const* d_in, const int* in_sizes, int n_in,
                              void* d_out, int out_size)
{
    const float* cls0     = (const float*)d_in[0];
    const float* box0     = (const float*)d_in[1];
    const float* cls1     = (const float*)d_in[2];
    const float* box1     = (const float*)d_in[3];
    const float* cls2     = (const float*)d_in[4];
    const float* box2     = (const float*)d_in[5];
    const float* gt_boxes = (const float*)d_in[6];
    const int*   gt_labels= (const int*)d_in[7];
    float*       out      = (float*)d_out;

    yolo_loss_kernel<<<BLOCKS, THREADS>>>(cls0, box0, cls1, box1, cls2, box2,
                                          gt_boxes, gt_labels, out);
}